// round 7
// baseline (speedup 1.0000x reference)
#include <cuda_runtime.h>
#include <math.h>

#define Bn   64
#define Sn   512
#define EMBn 128
#define HIDn 256
#define G4   1024
#define NTAG 9
#define HS2  260

// -------- persistent device scratch (no runtime allocs allowed) --------
__device__ float g_xz  [2u*Bn*Sn*G4];    // ((d*64+b)*512+s)*1024 + g
__device__ float g_hall[2u*Bn*Sn*HIDn];  // ((d*64+b)*512+s)*256  + j
__device__ int   g_lens[Bn];
__device__ int   g_flags[8][2][32];      // [bg][dir][member hg]

__global__ void k_reset() {
    int t = threadIdx.x;
    if (t < 8*2*32) ((int*)g_flags)[t] = 0;
}

// f32x2 packed helpers
__device__ __forceinline__ void ffma2(unsigned long long& acc,
                                      unsigned long long a,
                                      unsigned long long b) {
    asm("fma.rn.f32x2 %0, %1, %2, %0;" : "+l"(acc) : "l"(a), "l"(b));
}
__device__ __forceinline__ unsigned long long dup2(float x) {
    unsigned long long r;
    asm("mov.b64 %0, {%1, %1};" : "=l"(r) : "f"(x));
    return r;
}
__device__ __forceinline__ float2 unpack2(unsigned long long v) {
    float2 r;
    asm("mov.b64 {%0, %1}, %2;" : "=f"(r.x), "=f"(r.y) : "l"(v));
    return r;
}

// ---------------- lens: count nonzero tokens per row -------------------
__global__ void k_lens(const int* __restrict__ text, float* __restrict__ out_lens) {
    int b = blockIdx.x, lane = threadIdx.x;
    int cnt = 0;
    for (int s = lane; s < Sn; s += 32) cnt += (text[b*Sn + s] != 0);
    for (int o = 16; o > 0; o >>= 1) cnt += __shfl_down_sync(0xffffffffu, cnt, o);
    if (lane == 0) { g_lens[b] = cnt; out_lens[b] = (float)cnt; }
}

// ------------- input GEMM: xz = gather(emb,text) @ W + b  (both dirs) ---
__global__ __launch_bounds__(256) void k_input_gemm(
    const int* __restrict__ text, const float* __restrict__ emb,
    const float* __restrict__ Wf, const float* __restrict__ bf,
    const float* __restrict__ Wb, const float* __restrict__ bb)
{
    __shared__ float A_s[64*64];   // [k][m]
    __shared__ float B_s[64*64];   // [k][n]

    int m0 = blockIdx.y * 64;
    int n0 = blockIdx.x * 64;
    int d  = n0 >> 10;
    int gg0 = n0 - (d << 10);
    const float* W  = d ? Wb : Wf;
    const float* bs = d ? bb : bf;

    int tid = threadIdx.x;
    int tx = tid & 15, ty = tid >> 4;

    unsigned long long c2[4][2];
    #pragma unroll
    for (int i = 0; i < 4; i++) { c2[i][0] = 0ull; c2[i][1] = 0ull; }

    int r  = tid >> 2, cq = tid & 3;
    int tok = text[m0 + r];
    const float* erow = emb + (long)tok * EMBn;

    for (int kt = 0; kt < 2; kt++) {
        __syncthreads();
        #pragma unroll
        for (int i = 0; i < 4; i++) {
            float4 v = *(const float4*)(erow + kt*64 + cq*16 + i*4);
            int kb = cq*16 + i*4;
            A_s[(kb+0)*64 + r] = v.x;
            A_s[(kb+1)*64 + r] = v.y;
            A_s[(kb+2)*64 + r] = v.z;
            A_s[(kb+3)*64 + r] = v.w;
        }
        #pragma unroll
        for (int i = 0; i < 4; i++) {
            int kr = (tid >> 4) + i*16;
            float4 v = *(const float4*)(W + (long)(kt*64 + kr)*G4 + gg0 + (tid & 15)*4);
            *(float4*)&B_s[kr*64 + (tid & 15)*4] = v;
        }
        __syncthreads();

        #pragma unroll 8
        for (int k = 0; k < 64; k++) {
            float4 a = *(float4*)&A_s[k*64 + ty*4];
            ulonglong2 bu = *(ulonglong2*)&B_s[k*64 + tx*4];
            unsigned long long ad;
            ad = dup2(a.x); ffma2(c2[0][0], ad, bu.x); ffma2(c2[0][1], ad, bu.y);
            ad = dup2(a.y); ffma2(c2[1][0], ad, bu.x); ffma2(c2[1][1], ad, bu.y);
            ad = dup2(a.z); ffma2(c2[2][0], ad, bu.x); ffma2(c2[2][1], ad, bu.y);
            ad = dup2(a.w); ffma2(c2[3][0], ad, bu.x); ffma2(c2[3][1], ad, bu.y);
        }
    }

    float4 bv = *(const float4*)(bs + gg0 + tx*4);
    #pragma unroll
    for (int i = 0; i < 4; i++) {
        long m = m0 + ty*4 + i;
        float2 lo = unpack2(c2[i][0]);
        float2 hi = unpack2(c2[i][1]);
        float4 o;
        o.x = lo.x + bv.x; o.y = lo.y + bv.y;
        o.z = hi.x + bv.z; o.w = hi.y + bv.w;
        *(float4*)&g_xz[((long)d*32768 + m)*G4 + gg0 + tx*4] = o;
    }
}

// ------------------- persistent bidirectional LSTM ----------------------
// 128 blocks = (hg 0..15, bg 0..7). Block owns units [hg*16,+16), batches
// [bg*8,+8), BOTH directions (F then B each iteration; B compute hides F's
// barrier latency and vice versa). Exchange group = 16 blocks sharing bg.
// Threads 512 = (j16, bq2, kh16): 16-k slice, 4 batches per U fetch.
__global__ __launch_bounds__(512) void k_lstm(const float* __restrict__ Uf,
                                              const float* __restrict__ Ub)
{
    extern __shared__ float sm[];
    float* U_s  = sm;                         // 2 * 16384 : [dir][k][j][gate]
    float* hf_s = sm + 2*16384;               // 8 * 260
    float* hb_s = hf_s + 8*HS2;               // 8 * 260
    ulonglong2* red = (ulonglong2*)(hb_s + 8*HS2);   // 128*17 (reused F then B)

    int blk = blockIdx.x;
    int hg  = blk >> 3, bg = blk & 7;
    int j0  = hg * 16, b0 = bg * 8;

    int tid = threadIdx.x;
    int j   = tid & 15;
    int bq  = (tid >> 4) & 1;
    int kh  = tid >> 5;          // 0..15
    int k0  = kh << 4;

    for (int idx = tid; idx < 16384; idx += 512) {
        int k = idx >> 6, jy = (idx >> 2) & 15, g = idx & 3;
        U_s[idx]         = Uf[k*G4 + g*256 + j0 + jy];
        U_s[16384 + idx] = Ub[k*G4 + g*256 + j0 + jy];
    }
    for (int i = tid; i < 8*HS2; i += 512) { hf_s[i] = 0.f; hb_s[i] = 0.f; }

    int fb = tid >> 4, fj = tid & 15;     // finalizer mapping (tid<128)
    float cf = 0.f, cb = 0.f;
    __syncthreads();

    for (int r = 0; r < Sn; r++) {
        int sf = r, sb = Sn - 1 - r;

        float xf0, xf1, xf2, xf3, xb0, xb1, xb2, xb3;
        if (tid < 128) {
            const float* xp = g_xz + ((long)(b0 + fb)*Sn + sf)*G4 + j0 + fj;
            xf0 = __ldg(xp); xf1 = __ldg(xp+256); xf2 = __ldg(xp+512); xf3 = __ldg(xp+768);
            const float* xq = g_xz + ((long)(64 + b0 + fb)*Sn + sb)*G4 + j0 + fj;
            xb0 = __ldg(xq); xb1 = __ldg(xq+256); xb2 = __ldg(xq+512); xb3 = __ldg(xq+768);
        }

        // ================= FORWARD phase =================
        {
            unsigned long long a0[4], a1[4];
            #pragma unroll
            for (int i = 0; i < 4; i++) { a0[i] = 0ull; a1[i] = 0ull; }
            #pragma unroll
            for (int kk = 0; kk < 16; kk += 4) {
                int k = k0 + kk;
                ulonglong2 u0 = *(ulonglong2*)&U_s[((k+0)*16 + j)*4];
                ulonglong2 u1 = *(ulonglong2*)&U_s[((k+1)*16 + j)*4];
                ulonglong2 u2 = *(ulonglong2*)&U_s[((k+2)*16 + j)*4];
                ulonglong2 u3 = *(ulonglong2*)&U_s[((k+3)*16 + j)*4];
                #pragma unroll
                for (int i = 0; i < 4; i++) {
                    float4 hv = *(float4*)&hf_s[(bq*4 + i)*HS2 + k];
                    unsigned long long hd;
                    hd = dup2(hv.x); ffma2(a0[i], hd, u0.x); ffma2(a1[i], hd, u0.y);
                    hd = dup2(hv.y); ffma2(a0[i], hd, u1.x); ffma2(a1[i], hd, u1.y);
                    hd = dup2(hv.z); ffma2(a0[i], hd, u2.x); ffma2(a1[i], hd, u2.y);
                    hd = dup2(hv.w); ffma2(a0[i], hd, u3.x); ffma2(a1[i], hd, u3.y);
                }
            }
            #pragma unroll
            for (int i = 0; i < 4; i++) {
                ulonglong2 v; v.x = a0[i]; v.y = a1[i];
                red[((bq*4 + i)*16 + j)*17 + kh] = v;
            }
        }
        __syncthreads();
        if (tid < 128) {
            float zi = xf0, zf = xf1, zg = xf2, zo = xf3;
            #pragma unroll
            for (int q = 0; q < 16; q++) {
                ulonglong2 v = red[tid*17 + q];
                float2 p = unpack2(v.x), w = unpack2(v.y);
                zi += p.x; zf += p.y; zg += w.x; zo += w.y;
            }
            float ig = 1.f / (1.f + __expf(-zi));
            float fg = 1.f / (1.f + __expf(-zf));
            float gv = tanhf(zg);
            float og = 1.f / (1.f + __expf(-zo));
            cf = fg*cf + ig*gv;
            float hv = og * tanhf(cf);
            g_hall[((long)(b0 + fb)*Sn + sf)*HIDn + j0 + fj] = hv;
        }
        __syncthreads();
        if (tid == 0) {
            __threadfence();
            *((volatile int*)&g_flags[bg][0][hg]) = r + 1;
        }

        // ================= BACKWARD phase =================
        {
            unsigned long long a0[4], a1[4];
            #pragma unroll
            for (int i = 0; i < 4; i++) { a0[i] = 0ull; a1[i] = 0ull; }
            #pragma unroll
            for (int kk = 0; kk < 16; kk += 4) {
                int k = k0 + kk;
                ulonglong2 u0 = *(ulonglong2*)&U_s[16384 + ((k+0)*16 + j)*4];
                ulonglong2 u1 = *(ulonglong2*)&U_s[16384 + ((k+1)*16 + j)*4];
                ulonglong2 u2 = *(ulonglong2*)&U_s[16384 + ((k+2)*16 + j)*4];
                ulonglong2 u3 = *(ulonglong2*)&U_s[16384 + ((k+3)*16 + j)*4];
                #pragma unroll
                for (int i = 0; i < 4; i++) {
                    float4 hv = *(float4*)&hb_s[(bq*4 + i)*HS2 + k];
                    unsigned long long hd;
                    hd = dup2(hv.x); ffma2(a0[i], hd, u0.x); ffma2(a1[i], hd, u0.y);
                    hd = dup2(hv.y); ffma2(a0[i], hd, u1.x); ffma2(a1[i], hd, u1.y);
                    hd = dup2(hv.z); ffma2(a0[i], hd, u2.x); ffma2(a1[i], hd, u2.y);
                    hd = dup2(hv.w); ffma2(a0[i], hd, u3.x); ffma2(a1[i], hd, u3.y);
                }
            }
            #pragma unroll
            for (int i = 0; i < 4; i++) {
                ulonglong2 v; v.x = a0[i]; v.y = a1[i];
                red[((bq*4 + i)*16 + j)*17 + kh] = v;
            }
        }
        __syncthreads();
        if (tid < 128) {
            float zi = xb0, zf = xb1, zg = xb2, zo = xb3;
            #pragma unroll
            for (int q = 0; q < 16; q++) {
                ulonglong2 v = red[tid*17 + q];
                float2 p = unpack2(v.x), w = unpack2(v.y);
                zi += p.x; zf += p.y; zg += w.x; zo += w.y;
            }
            float ig = 1.f / (1.f + __expf(-zi));
            float fg = 1.f / (1.f + __expf(-zf));
            float gv = tanhf(zg);
            float og = 1.f / (1.f + __expf(-zo));
            cb = fg*cb + ig*gv;
            float hv = og * tanhf(cb);
            g_hall[((long)(64 + b0 + fb)*Sn + sb)*HIDn + j0 + fj] = hv;
        }
        __syncthreads();
        if (tid == 0) {
            __threadfence();
            *((volatile int*)&g_flags[bg][1][hg]) = r + 1;
        }

        // ============ wait peers + refill h (overlapped) ============
        if (r < Sn - 1) {
            if (tid < 16) {
                volatile int* f = &g_flags[bg][0][tid];
                while (*f < r + 1) { }
            }
            __syncthreads();
            int rb = tid >> 6, rj = (tid & 63) << 2;
            float4 vf = __ldcg((const float4*)&g_hall[((long)(b0 + rb)*Sn + sf)*HIDn + rj]);
            if (tid < 16) {
                volatile int* f = &g_flags[bg][1][tid];
                while (*f < r + 1) { }
            }
            __syncthreads();
            float4 vb = __ldcg((const float4*)&g_hall[((long)(64 + b0 + rb)*Sn + sb)*HIDn + rj]);
            *(float4*)&hf_s[rb*HS2 + rj] = vf;
            *(float4*)&hb_s[rb*HS2 + rj] = vb;
            __syncthreads();
        }
    }
}

// ---------------- logits = [h_fwd ; h_bwd] @ W_d + b_d ------------------
__global__ __launch_bounds__(256) void k_logits(
    const float* __restrict__ Wd, const float* __restrict__ bd,
    float* __restrict__ out)
{
    __shared__ float Wd_s[512*NTAG];
    int tid = threadIdx.x;
    for (int i = tid; i < 512*NTAG; i += 256) Wd_s[i] = Wd[i];
    __syncthreads();

    int wid = tid >> 5, lane = tid & 31;
    long m = (long)blockIdx.x * 8 + wid;

    float acc[NTAG];
    #pragma unroll
    for (int t = 0; t < NTAG; t++) acc[t] = 0.f;

    for (int k = lane; k < 512; k += 32) {
        int dd = k >> 8, jj = k & 255;
        float hv = g_hall[((long)dd*32768 + m)*HIDn + jj];
        #pragma unroll
        for (int t = 0; t < NTAG; t++) acc[t] += hv * Wd_s[k*NTAG + t];
    }
    #pragma unroll
    for (int t = 0; t < NTAG; t++)
        for (int o = 16; o > 0; o >>= 1)
            acc[t] += __shfl_down_sync(0xffffffffu, acc[t], o);
    if (lane == 0) {
        #pragma unroll
        for (int t = 0; t < NTAG; t++) out[m*NTAG + t] = acc[t] + bd[t];
    }
}

// --------------------------- CRF (warp per batch) -----------------------
__global__ __launch_bounds__(256) void k_crf(
    const float* __restrict__ logits, const int* __restrict__ labels,
    const float* __restrict__ trans, float* __restrict__ out_ll)
{
    __shared__ float tr[81];
    __shared__ float alpha[8][12];
    int tid = threadIdx.x;
    if (tid < 81) tr[tid] = trans[tid];
    __syncthreads();

    int wid = tid >> 5, lane = tid & 31;
    int b = blockIdx.x * 8 + wid;
    int len = g_lens[b];
    const float* lg = logits + (long)b * Sn * NTAG;
    const int*   lb = labels + (long)b * Sn;

    float sc = 0.f;
    for (int t = lane; t < Sn; t += 32) {
        int y = lb[t];
        if (t < len)     sc += lg[t*NTAG + y];
        if (t < len - 1) sc += tr[y*NTAG + lb[t+1]];
    }
    for (int o = 16; o > 0; o >>= 1) sc += __shfl_down_sync(0xffffffffu, sc, o);
    sc = __shfl_sync(0xffffffffu, sc, 0);

    if (lane < NTAG) alpha[wid][lane] = lg[lane];
    __syncwarp();
    for (int t = 1; t < Sn; t++) {
        if (t >= len) break;
        float na = 0.f;
        if (lane < NTAG) {
            float mx = -1e30f;
            #pragma unroll
            for (int i = 0; i < NTAG; i++) {
                float v = alpha[wid][i] + tr[i*NTAG + lane];
                mx = fmaxf(mx, v);
            }
            float s = 0.f;
            #pragma unroll
            for (int i = 0; i < NTAG; i++)
                s += __expf(alpha[wid][i] + tr[i*NTAG + lane] - mx);
            na = mx + __logf(s) + lg[t*NTAG + lane];
        }
        __syncwarp();
        if (lane < NTAG) alpha[wid][lane] = na;
        __syncwarp();
    }
    if (lane == 0) {
        float mx = -1e30f;
        for (int i = 0; i < NTAG; i++) mx = fmaxf(mx, alpha[wid][i]);
        float s = 0.f;
        for (int i = 0; i < NTAG; i++) s += __expf(alpha[wid][i] - mx);
        out_ll[b] = sc - (mx + __logf(s));
    }
}

// ----------------------------------------------------------------------
extern "C" void kernel_launch(void* const* d_in, const int* in_sizes, int n_in,
                              void* d_out, int out_size)
{
    const int*   text  = (const int*)  d_in[0];
    const int*   labels= (const int*)  d_in[1];
    const float* emb   = (const float*)d_in[2];
    const float* Wf    = (const float*)d_in[3];
    const float* Uf    = (const float*)d_in[4];
    const float* bf    = (const float*)d_in[5];
    const float* Wb    = (const float*)d_in[6];
    const float* Ub    = (const float*)d_in[7];
    const float* bb    = (const float*)d_in[8];
    const float* Wd    = (const float*)d_in[9];
    const float* bd    = (const float*)d_in[10];
    const float* trans = (const float*)d_in[11];

    float* out        = (float*)d_out;
    float* out_logits = out;                         // 64*512*9
    float* out_lens   = out + 64ll*512*9;            // 64
    float* out_ll     = out_lens + 64;               // 64

    // smem: U 2*16384*4 + h 2*8*260*4 + red 128*17*16 = 182528 B
    const int lstm_smem = 2*16384*4 + 2*8*HS2*4 + 128*17*16;
    cudaFuncSetAttribute(k_lstm, cudaFuncAttributeMaxDynamicSharedMemorySize, lstm_smem);

    k_reset<<<1, 512>>>();
    k_lens<<<64, 32>>>(text, out_lens);
    dim3 gg(32, 512);
    k_input_gemm<<<gg, 256>>>(text, emb, Wf, bf, Wb, bb);
    k_lstm<<<128, 512, lstm_smem>>>(Uf, Ub);
    k_logits<<<4096, 256>>>(Wd, bd, out_logits);
    k_crf<<<8, 256>>>(out_logits, labels, trans, out_ll);
}

// round 9
// speedup vs baseline: 1.0414x; 1.0414x over previous
#include <cuda_runtime.h>
#include <cuda_bf16.h>
#include <math.h>

#define Bn   64
#define Sn   512
#define EMBn 128
#define HIDn 256
#define G4   1024
#define NTAG 9
#define HS2  260

// -------- persistent device scratch (no runtime allocs allowed) --------
__device__ float g_xz  [2u*Bn*Sn*G4];    // ((d*64+b)*512+s)*1024 + g
__device__ float g_hall[2u*Bn*Sn*HIDn];  // ((d*64+b)*512+s)*256  + j
__device__ int   g_lens[Bn];
__device__ unsigned g_bars[8*32];        // 8 group counters, 128B apart
// split-bf16 operands for the tensor input GEMM
__device__ __nv_bfloat16 g_xc_hi[32768u*128];   // gathered emb rows [m][k], hi
__device__ __nv_bfloat16 g_xc_lo[32768u*128];   // lo
__device__ __nv_bfloat16 g_wt_hi[2u*1024*128];  // W^T rows [d*1024+n][k], hi
__device__ __nv_bfloat16 g_wt_lo[2u*1024*128];  // lo

__global__ void k_reset() {
    int t = threadIdx.x;
    if (t < 8*32) g_bars[t] = 0u;
}

// ---------------- f32x2 packed helpers (LSTM path) ---------------------
__device__ __forceinline__ void ffma2(unsigned long long& acc,
                                      unsigned long long a,
                                      unsigned long long b) {
    asm("fma.rn.f32x2 %0, %1, %2, %0;" : "+l"(acc) : "l"(a), "l"(b));
}
__device__ __forceinline__ unsigned long long dup2(float x) {
    unsigned long long r;
    asm("mov.b64 %0, {%1, %1};" : "=l"(r) : "f"(x));
    return r;
}
__device__ __forceinline__ float2 unpack2(unsigned long long v) {
    float2 r;
    asm("mov.b64 {%0, %1}, %2;" : "=f"(r.x), "=f"(r.y) : "l"(v));
    return r;
}

// ---------------- mma.sync helpers (compute_103-safe) ------------------
__device__ __forceinline__ unsigned smem_u32(const void* p) {
    unsigned a;
    asm("{ .reg .u64 t; cvta.to.shared.u64 t, %1; cvt.u32.u64 %0, t; }"
        : "=r"(a) : "l"(p));
    return a;
}
__device__ __forceinline__ void ldsm4(unsigned* r, unsigned addr) {
    asm volatile("ldmatrix.sync.aligned.m8n8.x4.shared.b16 {%0,%1,%2,%3}, [%4];"
        : "=r"(r[0]), "=r"(r[1]), "=r"(r[2]), "=r"(r[3]) : "r"(addr));
}
__device__ __forceinline__ void ldsm2(unsigned& r0, unsigned& r1, unsigned addr) {
    asm volatile("ldmatrix.sync.aligned.m8n8.x2.shared.b16 {%0,%1}, [%2];"
        : "=r"(r0), "=r"(r1) : "r"(addr));
}
__device__ __forceinline__ void mma16816(float* c, const unsigned* a,
                                         unsigned b0, unsigned b1) {
    asm volatile("mma.sync.aligned.m16n8k16.row.col.f32.bf16.bf16.f32 "
        "{%0,%1,%2,%3}, {%4,%5,%6,%7}, {%8,%9}, {%0,%1,%2,%3};"
        : "+f"(c[0]), "+f"(c[1]), "+f"(c[2]), "+f"(c[3])
        : "r"(a[0]), "r"(a[1]), "r"(a[2]), "r"(a[3]), "r"(b0), "r"(b1));
}

// ---------------- lens: count nonzero tokens per row -------------------
__global__ void k_lens(const int* __restrict__ text, float* __restrict__ out_lens) {
    int b = blockIdx.x, lane = threadIdx.x;
    int cnt = 0;
    for (int s = lane; s < Sn; s += 32) cnt += (text[b*Sn + s] != 0);
    for (int o = 16; o > 0; o >>= 1) cnt += __shfl_down_sync(0xffffffffu, cnt, o);
    if (lane == 0) { g_lens[b] = cnt; out_lens[b] = (float)cnt; }
}

// -------- prep: gathered embeddings -> hi/lo bf16 ----------------------
__global__ __launch_bounds__(128) void k_prepX(const int* __restrict__ text,
                                               const float* __restrict__ emb) {
    int m = blockIdx.x * 128 + threadIdx.x;     // 256 blocks
    int tok = text[m];
    const float4* er = (const float4*)(emb + (long)tok * EMBn);
    uint4* dh = ((uint4*)g_xc_hi) + (long)m * 16;
    uint4* dl = ((uint4*)g_xc_lo) + (long)m * 16;
    #pragma unroll 4
    for (int i = 0; i < 16; i++) {
        float4 a = er[2*i], b = er[2*i+1];
        float2 p0 = make_float2(a.x, a.y), p1 = make_float2(a.z, a.w);
        float2 p2 = make_float2(b.x, b.y), p3 = make_float2(b.z, b.w);
        __nv_bfloat162 h0 = __float22bfloat162_rn(p0);
        __nv_bfloat162 h1 = __float22bfloat162_rn(p1);
        __nv_bfloat162 h2 = __float22bfloat162_rn(p2);
        __nv_bfloat162 h3 = __float22bfloat162_rn(p3);
        float2 f0 = __bfloat1622float2(h0), f1 = __bfloat1622float2(h1);
        float2 f2 = __bfloat1622float2(h2), f3 = __bfloat1622float2(h3);
        __nv_bfloat162 l0 = __float22bfloat162_rn(make_float2(p0.x-f0.x, p0.y-f0.y));
        __nv_bfloat162 l1 = __float22bfloat162_rn(make_float2(p1.x-f1.x, p1.y-f1.y));
        __nv_bfloat162 l2 = __float22bfloat162_rn(make_float2(p2.x-f2.x, p2.y-f2.y));
        __nv_bfloat162 l3 = __float22bfloat162_rn(make_float2(p3.x-f3.x, p3.y-f3.y));
        uint4 uh, ul;
        uh.x = *(unsigned*)&h0; uh.y = *(unsigned*)&h1;
        uh.z = *(unsigned*)&h2; uh.w = *(unsigned*)&h3;
        ul.x = *(unsigned*)&l0; ul.y = *(unsigned*)&l1;
        ul.z = *(unsigned*)&l2; ul.w = *(unsigned*)&l3;
        dh[i] = uh; dl[i] = ul;
    }
}

// -------- prep: W^T -> hi/lo bf16 rows [d*1024+n][k] -------------------
__global__ __launch_bounds__(256) void k_prepW(const float* __restrict__ Wf,
                                               const float* __restrict__ Wb) {
    int t = blockIdx.x * 256 + threadIdx.x;     // 8 blocks -> 2048
    if (t >= 2048) return;
    int d = t >> 10, n = t & 1023;
    const float* W = d ? Wb : Wf;
    __nv_bfloat16* oh = g_wt_hi + (long)t * 128;
    __nv_bfloat16* ol = g_wt_lo + (long)t * 128;
    for (int k = 0; k < 128; k++) {
        float v = W[k * G4 + n];
        __nv_bfloat16 h = __float2bfloat16_rn(v);
        __nv_bfloat16 l = __float2bfloat16_rn(v - __bfloat162float(h));
        oh[k] = h; ol[k] = l;
    }
}

// -------- tensor input GEMM via mma.sync (split-bf16) -------------------
// z = xh*Wh + xh*Wl + xl*Wh, fp32 accumulators.
// Block: 128 tokens x 128 gate-cols, 256 thr (warps 4x2, warp tile 32x64).
// smem rows padded to 272B (conflict-free ldmatrix).
#define TGA 0
#define TGB0 34816
#define TGB1 69632
#define TG_SMEM 104448

__global__ __launch_bounds__(256) void k_tgemm(const float* __restrict__ bf_,
                                               const float* __restrict__ bb_) {
    extern __shared__ char smem[];
    unsigned sb = smem_u32(smem);
    int tid = threadIdx.x, wid = tid >> 5, lane = tid & 31;
    int wr = wid >> 1, wc = wid & 1;
    int m0 = blockIdx.y * 128;
    int n0 = blockIdx.x * 128;
    int d  = n0 >> 10, gg0 = n0 & 1023;

    // load B0 = Wh rows, B1 = Wl rows (128 n-rows x 128 k)
    {
        int row = tid >> 1, half = tid & 1;
        const uint4* s0 = ((const uint4*)g_wt_hi) + (long)(d*1024 + gg0 + row)*16 + half*8;
        const uint4* s1 = ((const uint4*)g_wt_lo) + (long)(d*1024 + gg0 + row)*16 + half*8;
        uint4* d0 = (uint4*)(smem + TGB0 + row*272 + half*128);
        uint4* d1 = (uint4*)(smem + TGB1 + row*272 + half*128);
        #pragma unroll
        for (int i = 0; i < 8; i++) { d0[i] = s0[i]; d1[i] = s1[i]; }
    }
    // load A = xh (128 m-rows x 128 k)
    {
        int row = tid >> 1, half = tid & 1;
        const uint4* s = ((const uint4*)g_xc_hi) + (long)(m0 + row)*16 + half*8;
        uint4* dA = (uint4*)(smem + TGA + row*272 + half*128);
        #pragma unroll
        for (int i = 0; i < 8; i++) dA[i] = s[i];
    }
    __syncthreads();

    float acc[2][8][4];
    #pragma unroll
    for (int mi = 0; mi < 2; mi++)
        #pragma unroll
        for (int nj = 0; nj < 8; nj++)
            #pragma unroll
            for (int q = 0; q < 4; q++) acc[mi][nj][q] = 0.f;

    unsigned a_row = (unsigned)(wr*32 + (lane & 15));
    unsigned b_rowbase = (unsigned)(wc*64 + (lane & 7));
    unsigned a_koff = (unsigned)((lane >> 4) * 8);
    unsigned b_koff = (unsigned)(((lane >> 3) & 1) * 8);

    #pragma unroll 1
    for (int phase = 0; phase < 2; phase++) {
        if (phase == 1) {
            __syncthreads();
            int row = tid >> 1, half = tid & 1;
            const uint4* s = ((const uint4*)g_xc_lo) + (long)(m0 + row)*16 + half*8;
            uint4* dA = (uint4*)(smem + TGA + row*272 + half*128);
            #pragma unroll
            for (int i = 0; i < 8; i++) dA[i] = s[i];
            __syncthreads();
        }
        #pragma unroll
        for (int kt = 0; kt < 8; kt++) {
            unsigned a0[4], a1[4];
            unsigned aaddr = sb + TGA + a_row*272 + (kt*16 + a_koff)*2;
            ldsm4(a0, aaddr);
            ldsm4(a1, aaddr + 16*272);
            #pragma unroll
            for (int nj = 0; nj < 8; nj++) {
                unsigned boff = (b_rowbase + nj*8)*272 + (kt*16 + b_koff)*2;
                unsigned b0, b1;
                ldsm2(b0, b1, sb + TGB0 + boff);
                mma16816(acc[0][nj], a0, b0, b1);
                mma16816(acc[1][nj], a1, b0, b1);
                if (phase == 0) {
                    unsigned c0, c1;
                    ldsm2(c0, c1, sb + TGB1 + boff);
                    mma16816(acc[0][nj], a0, c0, c1);
                    mma16816(acc[1][nj], a1, c0, c1);
                }
            }
        }
    }

    // store: D frag (m16n8 f32): c0,c1 row t/4 cols 2(t&3)+{0,1}; c2,c3 row+8
    const float* bias = d ? bb_ : bf_;
    #pragma unroll
    for (int mi = 0; mi < 2; mi++) {
        int m = m0 + wr*32 + mi*16 + (lane >> 2);
        float* rowp = g_xz + ((long)d*32768 + m)*G4;
        #pragma unroll
        for (int nj = 0; nj < 8; nj++) {
            int gg = gg0 + wc*64 + nj*8 + (lane & 3)*2;
            float bx = bias[gg], by = bias[gg+1];
            float2 v0, v1;
            v0.x = acc[mi][nj][0] + bx; v0.y = acc[mi][nj][1] + by;
            v1.x = acc[mi][nj][2] + bx; v1.y = acc[mi][nj][3] + by;
            *(float2*)(rowp + gg)          = v0;
            *(float2*)(rowp + 8*G4 + gg)   = v1;
        }
    }
}

// ------------------- persistent bidirectional LSTM (R6, best) ----------
__global__ __launch_bounds__(512) void k_lstm(const float* __restrict__ Uf,
                                              const float* __restrict__ Ub)
{
    extern __shared__ float sm[];
    float* h_s = sm;                                   // 16 * 260
    float* U_s = sm + 16*HS2;                          // 256*16*4 : [k][j][gate]
    unsigned long long* red = (unsigned long long*)(U_s + 256*64);  // 256*18 u64

    int blk = blockIdx.x;
    int d   = blk >> 6;
    int hg  = (blk >> 2) & 15;
    int bg  = blk & 3;
    int j0  = hg * 16;
    int b0  = bg * 16;
    int gid = d*4 + bg;                 // barrier group (16 members)

    int tid = threadIdx.x;
    int j   = tid & 15;
    int bq  = (tid >> 4) & 3;
    int kh  = tid >> 6;
    int k0  = kh << 5;
    const float* U = d ? Ub : Uf;

    for (int idx = tid; idx < 256*64; idx += 512) {
        int k  = idx >> 6;
        int jy = (idx >> 2) & 15;
        int g  = idx & 3;
        U_s[idx] = U[k*G4 + g*256 + j0 + jy];
    }
    for (int i = tid; i < 16*HS2; i += 512) h_s[i] = 0.f;

    float cstate = 0.f;
    __syncthreads();

    for (int r = 0; r < Sn; r++) {
        int s = d ? (Sn-1-r) : r;

        float x0, x1, x2, x3;
        if (tid < 256) {
            int fb = tid >> 4;
            const float* xp = g_xz + ((long)(d*64 + b0 + fb)*Sn + s)*G4 + j0 + j;
            x0 = __ldg(xp);
            x1 = __ldg(xp + 256);
            x2 = __ldg(xp + 512);
            x3 = __ldg(xp + 768);
        }
        if (r > 0) {
            int sp = d ? (s+1) : (s-1);
            #pragma unroll
            for (int i = 0; i < 2; i++) {
                int l  = i*512 + tid;
                int lb = l >> 6, lj = (l & 63) << 2;
                float4 v = *(const float4*)&g_hall[(((long)(d*64 + b0 + lb))*Sn + sp)*HIDn + lj];
                *(float4*)&h_s[lb*HS2 + lj] = v;
            }
        }
        __syncthreads();

        unsigned long long acc[4][2];
        #pragma unroll
        for (int i = 0; i < 4; i++) { acc[i][0] = 0ull; acc[i][1] = 0ull; }

        #pragma unroll 4
        for (int kk = 0; kk < 32; kk += 4) {
            int k = k0 + kk;
            float hrow[4][4];
            #pragma unroll
            for (int i = 0; i < 4; i++) {
                float4 v = *(float4*)&h_s[(bq*4 + i)*HS2 + k];
                hrow[i][0] = v.x; hrow[i][1] = v.y; hrow[i][2] = v.z; hrow[i][3] = v.w;
            }
            #pragma unroll
            for (int t = 0; t < 4; t++) {
                ulonglong2 u = *(ulonglong2*)&U_s[(k + t)*64 + j*4];
                #pragma unroll
                for (int i = 0; i < 4; i++) {
                    unsigned long long hd = dup2(hrow[i][t]);
                    ffma2(acc[i][0], hd, u.x);
                    ffma2(acc[i][1], hd, u.y);
                }
            }
        }

        #pragma unroll
        for (int i = 0; i < 4; i++) {
            int bj = (bq*4 + i)*16 + j;
            ulonglong2 v; v.x = acc[i][0]; v.y = acc[i][1];
            *(ulonglong2*)&red[bj*18 + kh*2] = v;
        }
        __syncthreads();

        if (tid < 256) {
            float zi = x0, zf = x1, zg = x2, zo = x3;
            #pragma unroll
            for (int q = 0; q < 8; q++) {
                ulonglong2 v = *(ulonglong2*)&red[tid*18 + q*2];
                float2 pif = unpack2(v.x), pgo = unpack2(v.y);
                zi += pif.x; zf += pif.y; zg += pgo.x; zo += pgo.y;
            }
            float ig = 1.f / (1.f + __expf(-zi));
            float fg = 1.f / (1.f + __expf(-zf));
            float gv = tanhf(zg);
            float og = 1.f / (1.f + __expf(-zo));
            cstate = fg*cstate + ig*gv;
            float hv = og * tanhf(cstate);
            int fb = tid >> 4;
            g_hall[(((long)(d*64 + b0 + fb))*Sn + s)*HIDn + j0 + j] = hv;
        }

        __threadfence();
        __syncthreads();
        if (tid == 0) {
            atomicAdd(&g_bars[gid*32], 1u);
            unsigned target = (unsigned)(r + 1) * 16u;
            while (*((volatile unsigned*)&g_bars[gid*32]) < target) { }
        }
        __syncthreads();
    }
}

// ---------------- logits = [h_fwd ; h_bwd] @ W_d + b_d ------------------
__global__ __launch_bounds__(256) void k_logits(
    const float* __restrict__ Wd, const float* __restrict__ bd,
    float* __restrict__ out)
{
    __shared__ float Wd_s[512*NTAG];
    int tid = threadIdx.x;
    for (int i = tid; i < 512*NTAG; i += 256) Wd_s[i] = Wd[i];
    __syncthreads();

    int wid = tid >> 5, lane = tid & 31;
    long m = (long)blockIdx.x * 8 + wid;

    float acc[NTAG];
    #pragma unroll
    for (int t = 0; t < NTAG; t++) acc[t] = 0.f;

    for (int k = lane; k < 512; k += 32) {
        int dd = k >> 8, jj = k & 255;
        float hv = g_hall[((long)dd*32768 + m)*HIDn + jj];
        #pragma unroll
        for (int t = 0; t < NTAG; t++) acc[t] += hv * Wd_s[k*NTAG + t];
    }
    #pragma unroll
    for (int t = 0; t < NTAG; t++)
        for (int o = 16; o > 0; o >>= 1)
            acc[t] += __shfl_down_sync(0xffffffffu, acc[t], o);
    if (lane == 0) {
        #pragma unroll
        for (int t = 0; t < NTAG; t++) out[m*NTAG + t] = acc[t] + bd[t];
    }
}

// --------------------------- CRF (warp per batch) -----------------------
__global__ __launch_bounds__(256) void k_crf(
    const float* __restrict__ logits, const int* __restrict__ labels,
    const float* __restrict__ trans, float* __restrict__ out_ll)
{
    __shared__ float tr[81];
    __shared__ float alpha[8][12];
    int tid = threadIdx.x;
    if (tid < 81) tr[tid] = trans[tid];
    __syncthreads();

    int wid = tid >> 5, lane = tid & 31;
    int b = blockIdx.x * 8 + wid;
    int len = g_lens[b];
    const float* lg = logits + (long)b * Sn * NTAG;
    const int*   lb = labels + (long)b * Sn;

    float sc = 0.f;
    for (int t = lane; t < Sn; t += 32) {
        int y = lb[t];
        if (t < len)     sc += lg[t*NTAG + y];
        if (t < len - 1) sc += tr[y*NTAG + lb[t+1]];
    }
    for (int o = 16; o > 0; o >>= 1) sc += __shfl_down_sync(0xffffffffu, sc, o);
    sc = __shfl_sync(0xffffffffu, sc, 0);

    if (lane < NTAG) alpha[wid][lane] = lg[lane];
    __syncwarp();
    for (int t = 1; t < Sn; t++) {
        if (t >= len) break;
        float na = 0.f;
        if (lane < NTAG) {
            float mx = -1e30f;
            #pragma unroll
            for (int i = 0; i < NTAG; i++) {
                float v = alpha[wid][i] + tr[i*NTAG + lane];
                mx = fmaxf(mx, v);
            }
            float s = 0.f;
            #pragma unroll
            for (int i = 0; i < NTAG; i++)
                s += __expf(alpha[wid][i] + tr[i*NTAG + lane] - mx);
            na = mx + __logf(s) + lg[t*NTAG + lane];
        }
        __syncwarp();
        if (lane < NTAG) alpha[wid][lane] = na;
        __syncwarp();
    }
    if (lane == 0) {
        float mx = -1e30f;
        for (int i = 0; i < NTAG; i++) mx = fmaxf(mx, alpha[wid][i]);
        float s = 0.f;
        for (int i = 0; i < NTAG; i++) s += __expf(alpha[wid][i] - mx);
        out_ll[b] = sc - (mx + __logf(s));
    }
}

// ----------------------------------------------------------------------
extern "C" void kernel_launch(void* const* d_in, const int* in_sizes, int n_in,
                              void* d_out, int out_size)
{
    const int*   text  = (const int*)  d_in[0];
    const int*   labels= (const int*)  d_in[1];
    const float* emb   = (const float*)d_in[2];
    const float* Wf    = (const float*)d_in[3];
    const float* Uf    = (const float*)d_in[4];
    const float* bf    = (const float*)d_in[5];
    const float* Wb    = (const float*)d_in[6];
    const float* Ub    = (const float*)d_in[7];
    const float* bb    = (const float*)d_in[8];
    const float* Wd    = (const float*)d_in[9];
    const float* bd    = (const float*)d_in[10];
    const float* trans = (const float*)d_in[11];

    float* out        = (float*)d_out;
    float* out_logits = out;                         // 64*512*9
    float* out_lens   = out + 64ll*512*9;            // 64
    float* out_ll     = out_lens + 64;               // 64

    const int lstm_smem = 16*HS2*4 + 256*64*4 + 256*18*8;   // 119040 B
    cudaFuncSetAttribute(k_lstm, cudaFuncAttributeMaxDynamicSharedMemorySize, lstm_smem);
    cudaFuncSetAttribute(k_tgemm, cudaFuncAttributeMaxDynamicSharedMemorySize, TG_SMEM);

    k_reset<<<1, 256>>>();
    k_lens<<<64, 32>>>(text, out_lens);
    k_prepW<<<8, 256>>>(Wf, Wb);
    k_prepX<<<256, 128>>>(text, emb);
    dim3 tg(16, 256);
    k_tgemm<<<tg, 256, TG_SMEM>>>(bf, bb);
    k_lstm<<<128, 512, lstm_smem>>>(Uf, Ub);
    k_logits<<<4096, 256>>>(Wd, bd, out_logits);
    k_crf<<<8, 256>>>(out_logits, labels, trans, out_ll);
}

// round 11
// speedup vs baseline: 1.1390x; 1.0938x over previous
#include <cuda_runtime.h>
#include <cuda_bf16.h>
#include <math.h>

#define Bn   64
#define Sn   512
#define EMBn 128
#define HIDn 256
#define G4   1024
#define NTAG 9

// -------- persistent device scratch (no runtime allocs allowed) --------
__device__ float g_xz  [2u*Bn*Sn*G4];    // ((d*64+b)*512+s)*1024 + g
__device__ float g_hall[2u*Bn*Sn*HIDn];  // ((d*64+b)*512+s)*256  + j
__device__ int   g_lens[Bn];
__device__ unsigned g_bars[8*32];        // 8 group counters, 128B apart
// split-bf16 operands for the tensor input GEMM
__device__ __nv_bfloat16 g_xc_hi[32768u*128];   // gathered emb rows [m][k], hi
__device__ __nv_bfloat16 g_xc_lo[32768u*128];   // lo
__device__ __nv_bfloat16 g_wt_hi[2u*1024*128];  // W^T rows [d*1024+n][k], hi
__device__ __nv_bfloat16 g_wt_lo[2u*1024*128];  // lo
// split-bf16 U (reordered cols n' = unit*4 + gate) for tensor LSTM
__device__ __nv_bfloat16 g_u2h[2u*1024*256];    // [d*1024+n'][k]
__device__ __nv_bfloat16 g_u2l[2u*1024*256];
// split-bf16 h exchange (per step)
__device__ __nv_bfloat16 g_hx_hi[2u*Bn*Sn*HIDn];
__device__ __nv_bfloat16 g_hx_lo[2u*Bn*Sn*HIDn];

__global__ void k_reset() {
    int t = threadIdx.x;
    if (t < 8*32) g_bars[t] = 0u;
}

// ---------------- mma.sync helpers (compute_103-safe) ------------------
__device__ __forceinline__ unsigned smem_u32(const void* p) {
    unsigned a;
    asm("{ .reg .u64 t; cvta.to.shared.u64 t, %1; cvt.u32.u64 %0, t; }"
        : "=r"(a) : "l"(p));
    return a;
}
__device__ __forceinline__ void ldsm4(unsigned* r, unsigned addr) {
    asm volatile("ldmatrix.sync.aligned.m8n8.x4.shared.b16 {%0,%1,%2,%3}, [%4];"
        : "=r"(r[0]), "=r"(r[1]), "=r"(r[2]), "=r"(r[3]) : "r"(addr));
}
__device__ __forceinline__ void ldsm2(unsigned& r0, unsigned& r1, unsigned addr) {
    asm volatile("ldmatrix.sync.aligned.m8n8.x2.shared.b16 {%0,%1}, [%2];"
        : "=r"(r0), "=r"(r1) : "r"(addr));
}
__device__ __forceinline__ void mma16816(float* c, const unsigned* a,
                                         unsigned b0, unsigned b1) {
    asm volatile("mma.sync.aligned.m16n8k16.row.col.f32.bf16.bf16.f32 "
        "{%0,%1,%2,%3}, {%4,%5,%6,%7}, {%8,%9}, {%0,%1,%2,%3};"
        : "+f"(c[0]), "+f"(c[1]), "+f"(c[2]), "+f"(c[3])
        : "r"(a[0]), "r"(a[1]), "r"(a[2]), "r"(a[3]), "r"(b0), "r"(b1));
}

// ---------------- lens: count nonzero tokens per row -------------------
__global__ void k_lens(const int* __restrict__ text, float* __restrict__ out_lens) {
    int b = blockIdx.x, lane = threadIdx.x;
    int cnt = 0;
    for (int s = lane; s < Sn; s += 32) cnt += (text[b*Sn + s] != 0);
    for (int o = 16; o > 0; o >>= 1) cnt += __shfl_down_sync(0xffffffffu, cnt, o);
    if (lane == 0) { g_lens[b] = cnt; out_lens[b] = (float)cnt; }
}

// -------- prep: gathered embeddings -> hi/lo bf16 ----------------------
__global__ __launch_bounds__(128) void k_prepX(const int* __restrict__ text,
                                               const float* __restrict__ emb) {
    int m = blockIdx.x * 128 + threadIdx.x;     // 256 blocks
    int tok = text[m];
    const float4* er = (const float4*)(emb + (long)tok * EMBn);
    uint4* dh = ((uint4*)g_xc_hi) + (long)m * 16;
    uint4* dl = ((uint4*)g_xc_lo) + (long)m * 16;
    #pragma unroll 4
    for (int i = 0; i < 16; i++) {
        float4 a = er[2*i], b = er[2*i+1];
        float2 p0 = make_float2(a.x, a.y), p1 = make_float2(a.z, a.w);
        float2 p2 = make_float2(b.x, b.y), p3 = make_float2(b.z, b.w);
        __nv_bfloat162 h0 = __float22bfloat162_rn(p0);
        __nv_bfloat162 h1 = __float22bfloat162_rn(p1);
        __nv_bfloat162 h2 = __float22bfloat162_rn(p2);
        __nv_bfloat162 h3 = __float22bfloat162_rn(p3);
        float2 f0 = __bfloat1622float2(h0), f1 = __bfloat1622float2(h1);
        float2 f2 = __bfloat1622float2(h2), f3 = __bfloat1622float2(h3);
        __nv_bfloat162 l0 = __float22bfloat162_rn(make_float2(p0.x-f0.x, p0.y-f0.y));
        __nv_bfloat162 l1 = __float22bfloat162_rn(make_float2(p1.x-f1.x, p1.y-f1.y));
        __nv_bfloat162 l2 = __float22bfloat162_rn(make_float2(p2.x-f2.x, p2.y-f2.y));
        __nv_bfloat162 l3 = __float22bfloat162_rn(make_float2(p3.x-f3.x, p3.y-f3.y));
        uint4 uh, ul;
        uh.x = *(unsigned*)&h0; uh.y = *(unsigned*)&h1;
        uh.z = *(unsigned*)&h2; uh.w = *(unsigned*)&h3;
        ul.x = *(unsigned*)&l0; ul.y = *(unsigned*)&l1;
        ul.z = *(unsigned*)&l2; ul.w = *(unsigned*)&l3;
        dh[i] = uh; dl[i] = ul;
    }
}

// -------- prep: W^T -> hi/lo bf16 rows [d*1024+n][k] -------------------
__global__ __launch_bounds__(256) void k_prepW(const float* __restrict__ Wf,
                                               const float* __restrict__ Wb) {
    int t = blockIdx.x * 256 + threadIdx.x;     // 8 blocks -> 2048
    if (t >= 2048) return;
    int d = t >> 10, n = t & 1023;
    const float* W = d ? Wb : Wf;
    __nv_bfloat16* oh = g_wt_hi + (long)t * 128;
    __nv_bfloat16* ol = g_wt_lo + (long)t * 128;
    for (int k = 0; k < 128; k++) {
        float v = W[k * G4 + n];
        __nv_bfloat16 h = __float2bfloat16_rn(v);
        __nv_bfloat16 l = __float2bfloat16_rn(v - __bfloat162float(h));
        oh[k] = h; ol[k] = l;
    }
}

// -------- prep: U -> reordered hi/lo bf16 rows [d*1024+n'][k] ----------
// n' = unit*4 + gate  (source col = gate*256 + unit)
__global__ __launch_bounds__(256) void k_prepU(const float* __restrict__ Uf,
                                               const float* __restrict__ Ub) {
    int t = blockIdx.x * 256 + threadIdx.x;     // 8 blocks -> 2048
    if (t >= 2048) return;
    int d = t >> 10, np = t & 1023;
    int j = np >> 2, g = np & 3;
    const float* U = d ? Ub : Uf;
    __nv_bfloat16* oh = g_u2h + (long)t * 256;
    __nv_bfloat16* ol = g_u2l + (long)t * 256;
    for (int k = 0; k < 256; k++) {
        float v = U[k * G4 + g*256 + j];
        __nv_bfloat16 h = __float2bfloat16_rn(v);
        __nv_bfloat16 l = __float2bfloat16_rn(v - __bfloat162float(h));
        oh[k] = h; ol[k] = l;
    }
}

// -------- tensor input GEMM via mma.sync (split-bf16) — R9 proven ------
#define TGA 0
#define TGB0 34816
#define TGB1 69632
#define TG_SMEM 104448

__global__ __launch_bounds__(256) void k_tgemm(const float* __restrict__ bf_,
                                               const float* __restrict__ bb_) {
    extern __shared__ char smem[];
    unsigned sb = smem_u32(smem);
    int tid = threadIdx.x, wid = tid >> 5, lane = tid & 31;
    int wr = wid >> 1, wc = wid & 1;
    int m0 = blockIdx.y * 128;
    int n0 = blockIdx.x * 128;
    int d  = n0 >> 10, gg0 = n0 & 1023;

    {
        int row = tid >> 1, half = tid & 1;
        const uint4* s0 = ((const uint4*)g_wt_hi) + (long)(d*1024 + gg0 + row)*16 + half*8;
        const uint4* s1 = ((const uint4*)g_wt_lo) + (long)(d*1024 + gg0 + row)*16 + half*8;
        uint4* d0 = (uint4*)(smem + TGB0 + row*272 + half*128);
        uint4* d1 = (uint4*)(smem + TGB1 + row*272 + half*128);
        #pragma unroll
        for (int i = 0; i < 8; i++) { d0[i] = s0[i]; d1[i] = s1[i]; }
    }
    {
        int row = tid >> 1, half = tid & 1;
        const uint4* s = ((const uint4*)g_xc_hi) + (long)(m0 + row)*16 + half*8;
        uint4* dA = (uint4*)(smem + TGA + row*272 + half*128);
        #pragma unroll
        for (int i = 0; i < 8; i++) dA[i] = s[i];
    }
    __syncthreads();

    float acc[2][8][4];
    #pragma unroll
    for (int mi = 0; mi < 2; mi++)
        #pragma unroll
        for (int nj = 0; nj < 8; nj++)
            #pragma unroll
            for (int q = 0; q < 4; q++) acc[mi][nj][q] = 0.f;

    unsigned a_row = (unsigned)(wr*32 + (lane & 15));
    unsigned b_rowbase = (unsigned)(wc*64 + (lane & 7));
    unsigned a_koff = (unsigned)((lane >> 4) * 8);
    unsigned b_koff = (unsigned)(((lane >> 3) & 1) * 8);

    #pragma unroll 1
    for (int phase = 0; phase < 2; phase++) {
        if (phase == 1) {
            __syncthreads();
            int row = tid >> 1, half = tid & 1;
            const uint4* s = ((const uint4*)g_xc_lo) + (long)(m0 + row)*16 + half*8;
            uint4* dA = (uint4*)(smem + TGA + row*272 + half*128);
            #pragma unroll
            for (int i = 0; i < 8; i++) dA[i] = s[i];
            __syncthreads();
        }
        #pragma unroll
        for (int kt = 0; kt < 8; kt++) {
            unsigned a0[4], a1[4];
            unsigned aaddr = sb + TGA + a_row*272 + (kt*16 + a_koff)*2;
            ldsm4(a0, aaddr);
            ldsm4(a1, aaddr + 16*272);
            #pragma unroll
            for (int nj = 0; nj < 8; nj++) {
                unsigned boff = (b_rowbase + nj*8)*272 + (kt*16 + b_koff)*2;
                unsigned b0, b1;
                ldsm2(b0, b1, sb + TGB0 + boff);
                mma16816(acc[0][nj], a0, b0, b1);
                mma16816(acc[1][nj], a1, b0, b1);
                if (phase == 0) {
                    unsigned c0, c1;
                    ldsm2(c0, c1, sb + TGB1 + boff);
                    mma16816(acc[0][nj], a0, c0, c1);
                    mma16816(acc[1][nj], a1, c0, c1);
                }
            }
        }
    }

    const float* bias = d ? bb_ : bf_;
    #pragma unroll
    for (int mi = 0; mi < 2; mi++) {
        int m = m0 + wr*32 + mi*16 + (lane >> 2);
        float* rowp = g_xz + ((long)d*32768 + m)*G4;
        #pragma unroll
        for (int nj = 0; nj < 8; nj++) {
            int gg = gg0 + wc*64 + nj*8 + (lane & 3)*2;
            float bx = bias[gg], by = bias[gg+1];
            float2 v0, v1;
            v0.x = acc[mi][nj][0] + bx; v0.y = acc[mi][nj][1] + by;
            v1.x = acc[mi][nj][2] + bx; v1.y = acc[mi][nj][3] + by;
            *(float2*)(rowp + gg)          = v0;
            *(float2*)(rowp + 8*G4 + gg)   = v1;
        }
    }
}

// ------------------- tensor-core persistent BiLSTM ----------------------
// 128 blocks = (d, hg 0..15, bg 0..3), 256 threads = 8 warps (one n8 tile
// each over 64 n'-cols). Block: dir d, units [hg*16,+16), batches
// [bg*16,+16). z tile = h[16,256] @ U'[256,64] via split-bf16 mma.sync with
// B (U') fragments register-resident all 512 steps. 3 independent
// accumulator chains (hh*Uh / hh*Ul / hl*Uh) cut mma dependency depth 3x.
// Barrier group = 16 blocks sharing (d,bg), flag counter per group.
#define LS_U   0                     // U' stage: 64 rows * 528 B * 2 (hi,lo)
#define LS_AHH 67584                 // 16 * 528
#define LS_AHL (67584 + 8448)
#define LS_SMEM (67584 + 2*8448)

__global__ __launch_bounds__(256) void k_lstm() {
    extern __shared__ char smem[];
    unsigned sb = smem_u32(smem);

    int blk = blockIdx.x;
    int d  = blk >> 6;
    int hg = (blk >> 2) & 15;
    int bg = blk & 3;
    int b0 = bg * 16;
    int gid = d*4 + bg;

    int tid = threadIdx.x, wid = tid >> 5, lane = tid & 31;
    int nj = wid;                       // warp's n8 tile (0..7)

    // stage U' rows [hg*64, +64), hi+lo  (64 rows x 32 uint4 each)
    for (int i = tid; i < 64*32; i += 256) {
        int row = i >> 5, c = i & 31;
        long src = ((long)(d*1024 + hg*64 + row)) * 256;
        uint4 vh = *(((const uint4*)(g_u2h + src)) + c);
        uint4 vl = *(((const uint4*)(g_u2l + src)) + c);
        *(uint4*)(smem + LS_U + row*528 + c*16)            = vh;
        *(uint4*)(smem + LS_U + 64*528 + row*528 + c*16)   = vl;
    }
    // zero A staging (h0 = 0): 8448 B = 2112 floats each
    for (int i = tid; i < 2112; i += 256) {
        *(float*)(smem + LS_AHH + i*4) = 0.f;
        *(float*)(smem + LS_AHL + i*4) = 0.f;
    }
    __syncthreads();

    // preload B fragments (64 regs): bh/bl[kt][2]
    unsigned bh[16][2], bl[16][2];
    {
        unsigned brow = (unsigned)(nj*8 + (lane & 7));
        unsigned koff = (unsigned)(((lane >> 3) & 1) * 8);
        #pragma unroll
        for (int kt = 0; kt < 16; kt++) {
            ldsm2(bh[kt][0], bh[kt][1], sb + LS_U + brow*528 + (kt*16 + koff)*2);
            ldsm2(bl[kt][0], bl[kt][1], sb + LS_U + 64*528 + brow*528 + (kt*16 + koff)*2);
        }
    }

    int row = lane >> 2;                      // batch-in-tile (0..7); +8 for c2/c3
    int p   = lane & 3;
    int jj  = nj*2 + (p >> 1);                // unit-in-block (0..15)
    int jgl = hg*16 + jj;                     // global unit (0..255)
    bool fin = (lane & 1) == 0;
    float cst0 = 0.f, cst1 = 0.f;

    unsigned a_row = (unsigned)(lane & 15);
    unsigned a_koff = (unsigned)((lane >> 4) * 8);

    for (int r = 0; r < Sn; r++) {
        int s = d ? (Sn-1-r) : r;

        // prefetch x (even lanes): gates of (b, jgl) and (b+8, jgl)
        float x0=0,x1=0,x2=0,x3=0,x4=0,x5=0,x6=0,x7=0;
        if (fin) {
            const float* xp = g_xz + (((long)(d*64 + b0 + row))*Sn + s)*G4 + jgl;
            x0 = __ldg(xp);       x1 = __ldg(xp + 256);
            x2 = __ldg(xp + 512); x3 = __ldg(xp + 768);
            const float* xq = xp + (long)8*Sn*G4;
            x4 = __ldg(xq);       x5 = __ldg(xq + 256);
            x6 = __ldg(xq + 512); x7 = __ldg(xq + 768);
        }
        // stage prev h (hi/lo) into A smem: 16 rows x 32 uint4 = 512
        if (r > 0) {
            int sp = d ? (s+1) : (s-1);
            #pragma unroll
            for (int i = 0; i < 2; i++) {
                int l = i*256 + tid;
                int ar = l >> 5, c = l & 31;
                long src = (((long)(d*64 + b0 + ar))*Sn + sp)*HIDn;
                uint4 vh = __ldcg(((const uint4*)(g_hx_hi + src)) + c);
                uint4 vl = __ldcg(((const uint4*)(g_hx_lo + src)) + c);
                *(uint4*)(smem + LS_AHH + ar*528 + c*16) = vh;
                *(uint4*)(smem + LS_AHL + ar*528 + c*16) = vl;
            }
        }
        __syncthreads();

        float aA[4] = {0,0,0,0}, aB[4] = {0,0,0,0}, aC[4] = {0,0,0,0};
        #pragma unroll
        for (int kt = 0; kt < 16; kt++) {
            unsigned ah[4], al[4];
            ldsm4(ah, sb + LS_AHH + a_row*528 + (kt*16 + a_koff)*2);
            mma16816(aA, ah, bh[kt][0], bh[kt][1]);
            mma16816(aB, ah, bl[kt][0], bl[kt][1]);
            ldsm4(al, sb + LS_AHL + a_row*528 + (kt*16 + a_koff)*2);
            mma16816(aC, al, bh[kt][0], bh[kt][1]);
        }
        __syncthreads();   // A smem free for next step's staging

        float acc0 = aA[0] + aB[0] + aC[0];
        float acc1 = aA[1] + aB[1] + aC[1];
        float acc2 = aA[2] + aB[2] + aC[2];
        float acc3 = aA[3] + aB[3] + aC[3];

        // pair-exchange: even lane gets partner's (g2,g3)
        float rc0 = __shfl_xor_sync(0xffffffffu, acc0, 1);
        float rc1 = __shfl_xor_sync(0xffffffffu, acc1, 1);
        float rc2 = __shfl_xor_sync(0xffffffffu, acc2, 1);
        float rc3 = __shfl_xor_sync(0xffffffffu, acc3, 1);

        if (fin) {
            {   // batch b0+row
                float zi = x0 + acc0, zf = x1 + acc1;
                float zg = x2 + rc0,  zo = x3 + rc1;
                float ig = 1.f / (1.f + __expf(-zi));
                float fg = 1.f / (1.f + __expf(-zf));
                float gv = tanhf(zg);
                float og = 1.f / (1.f + __expf(-zo));
                cst0 = fg*cst0 + ig*gv;
                float hv = og * tanhf(cst0);
                long o0 = (((long)(d*64 + b0 + row))*Sn + s)*HIDn + jgl;
                g_hall[o0] = hv;
                __nv_bfloat16 hh = __float2bfloat16_rn(hv);
                g_hx_hi[o0] = hh;
                g_hx_lo[o0] = __float2bfloat16_rn(hv - __bfloat162float(hh));
            }
            {   // batch b0+row+8
                float zi = x4 + acc2, zf = x5 + acc3;
                float zg = x6 + rc2,  zo = x7 + rc3;
                float ig = 1.f / (1.f + __expf(-zi));
                float fg = 1.f / (1.f + __expf(-zf));
                float gv = tanhf(zg);
                float og = 1.f / (1.f + __expf(-zo));
                cst1 = fg*cst1 + ig*gv;
                float hv = og * tanhf(cst1);
                long o1 = (((long)(d*64 + b0 + row + 8))*Sn + s)*HIDn + jgl;
                g_hall[o1] = hv;
                __nv_bfloat16 hh = __float2bfloat16_rn(hv);
                g_hx_hi[o1] = hh;
                g_hx_lo[o1] = __float2bfloat16_rn(hv - __bfloat162float(hh));
            }
        }

        // group barrier (16 blocks sharing (d,bg))
        __threadfence();
        __syncthreads();
        if (tid == 0) {
            atomicAdd(&g_bars[gid*32], 1u);
            unsigned target = (unsigned)(r + 1) * 16u;
            while (*((volatile unsigned*)&g_bars[gid*32]) < target) { }
        }
        __syncthreads();
    }
}

// ---------------- logits = [h_fwd ; h_bwd] @ W_d + b_d ------------------
__global__ __launch_bounds__(256) void k_logits(
    const float* __restrict__ Wd, const float* __restrict__ bd,
    float* __restrict__ out)
{
    __shared__ float Wd_s[512*NTAG];
    int tid = threadIdx.x;
    for (int i = tid; i < 512*NTAG; i += 256) Wd_s[i] = Wd[i];
    __syncthreads();

    int wid = tid >> 5, lane = tid & 31;
    long m = (long)blockIdx.x * 8 + wid;

    float acc[NTAG];
    #pragma unroll
    for (int t = 0; t < NTAG; t++) acc[t] = 0.f;

    for (int k = lane; k < 512; k += 32) {
        int dd = k >> 8, jj = k & 255;
        float hv = g_hall[((long)dd*32768 + m)*HIDn + jj];
        #pragma unroll
        for (int t = 0; t < NTAG; t++) acc[t] += hv * Wd_s[k*NTAG + t];
    }
    #pragma unroll
    for (int t = 0; t < NTAG; t++)
        for (int o = 16; o > 0; o >>= 1)
            acc[t] += __shfl_down_sync(0xffffffffu, acc[t], o);
    if (lane == 0) {
        #pragma unroll
        for (int t = 0; t < NTAG; t++) out[m*NTAG + t] = acc[t] + bd[t];
    }
}

// --------------------------- CRF (warp per batch) -----------------------
__global__ __launch_bounds__(256) void k_crf(
    const float* __restrict__ logits, const int* __restrict__ labels,
    const float* __restrict__ trans, float* __restrict__ out_ll)
{
    __shared__ float tr[81];
    __shared__ float alpha[8][12];
    int tid = threadIdx.x;
    if (tid < 81) tr[tid] = trans[tid];
    __syncthreads();

    int wid = tid >> 5, lane = tid & 31;
    int b = blockIdx.x * 8 + wid;
    int len = g_lens[b];
    const float* lg = logits + (long)b * Sn * NTAG;
    const int*   lb = labels + (long)b * Sn;

    float sc = 0.f;
    for (int t = lane; t < Sn; t += 32) {
        int y = lb[t];
        if (t < len)     sc += lg[t*NTAG + y];
        if (t < len - 1) sc += tr[y*NTAG + lb[t+1]];
    }
    for (int o = 16; o > 0; o >>= 1) sc += __shfl_down_sync(0xffffffffu, sc, o);
    sc = __shfl_sync(0xffffffffu, sc, 0);

    if (lane < NTAG) alpha[wid][lane] = lg[lane];
    __syncwarp();
    for (int t = 1; t < Sn; t++) {
        if (t >= len) break;
        float na = 0.f;
        if (lane < NTAG) {
            float mx = -1e30f;
            #pragma unroll
            for (int i = 0; i < NTAG; i++) {
                float v = alpha[wid][i] + tr[i*NTAG + lane];
                mx = fmaxf(mx, v);
            }
            float s = 0.f;
            #pragma unroll
            for (int i = 0; i < NTAG; i++)
                s += __expf(alpha[wid][i] + tr[i*NTAG + lane] - mx);
            na = mx + __logf(s) + lg[t*NTAG + lane];
        }
        __syncwarp();
        if (lane < NTAG) alpha[wid][lane] = na;
        __syncwarp();
    }
    if (lane == 0) {
        float mx = -1e30f;
        for (int i = 0; i < NTAG; i++) mx = fmaxf(mx, alpha[wid][i]);
        float s = 0.f;
        for (int i = 0; i < NTAG; i++) s += __expf(alpha[wid][i] - mx);
        out_ll[b] = sc - (mx + __logf(s));
    }
}

// ----------------------------------------------------------------------
extern "C" void kernel_launch(void* const* d_in, const int* in_sizes, int n_in,
                              void* d_out, int out_size)
{
    const int*   text  = (const int*)  d_in[0];
    const int*   labels= (const int*)  d_in[1];
    const float* emb   = (const float*)d_in[2];
    const float* Wf    = (const float*)d_in[3];
    const float* Uf    = (const float*)d_in[4];
    const float* bf    = (const float*)d_in[5];
    const float* Wb    = (const float*)d_in[6];
    const float* Ub    = (const float*)d_in[7];
    const float* bb    = (const float*)d_in[8];
    const float* Wd    = (const float*)d_in[9];
    const float* bd    = (const float*)d_in[10];
    const float* trans = (const float*)d_in[11];

    float* out        = (float*)d_out;
    float* out_logits = out;                         // 64*512*9
    float* out_lens   = out + 64ll*512*9;            // 64
    float* out_ll     = out_lens + 64;               // 64

    cudaFuncSetAttribute(k_lstm, cudaFuncAttributeMaxDynamicSharedMemorySize, LS_SMEM);
    cudaFuncSetAttribute(k_tgemm, cudaFuncAttributeMaxDynamicSharedMemorySize, TG_SMEM);

    k_reset<<<1, 256>>>();
    k_lens<<<64, 32>>>(text, out_lens);
    k_prepW<<<8, 256>>>(Wf, Wb);
    k_prepU<<<8, 256>>>(Uf, Ub);
    k_prepX<<<256, 128>>>(text, emb);
    dim3 tg(16, 256);
    k_tgemm<<<tg, 256, TG_SMEM>>>(bf, bb);
    k_lstm<<<128, 256, LS_SMEM>>>();
    k_logits<<<4096, 256>>>(Wd, bd, out_logits);
    k_crf<<<8, 256>>>(out_logits, labels, trans, out_ll);
}